// round 14
// baseline (speedup 1.0000x reference)
#include <cuda_runtime.h>
#include <cuda_fp16.h>
#include <cstdint>
#include <math.h>

// ---------------- problem dims ----------------
#define NB   8
#define LB   4096
#define HB   1024
#define KB   1024
#define MTOT (NB * LB)          // 32768
#define SEG    32
#define SEGLEN (LB / SEG)       // 128

// ---------------- GEMM tiling -----------------
#define BM 128                  // M rows / CTA  (== SEGLEN -> CTA owns one segment)
#define BNP 64                  // o-pairs / CTA (B tile = 128 interleaved rows)
#define BKE 64                  // K fp16 elems per stage (128B rows)
#define NKT (KB / BKE)          // 16
#define PIPE 3

// per-stage smem tiles (bytes): 128 rows x 128B each
#define T_A  0
#define T_B  16384
#define STAGE_BYTES 32768
#define SMEM_DYN (PIPE * STAGE_BYTES)   // 96 KB -> 2 CTAs/SM

#define AV_STRIDE 65            // half2 row stride in reused smem (bank pad)

// ---------------- device scratch ----------------
__device__ __half2 g_av[(size_t)MTOT * HB];    // packed (a, v) = 128 MB
__device__ float  g_Aseg[NB * SEG * HB];
__device__ float  g_Bseg[NB * SEG * HB];
__device__ float  g_Cin [NB * SEG * HB];
__device__ __half g_xh[(size_t)MTOT * KB];     // 64 MB
__device__ __half g_wh[(size_t)2 * HB * KB];   // 4 MB

// ---------------- helpers ----------------
__device__ __forceinline__ uint32_t smem_u32(const void* p) {
    uint32_t a;
    asm("{ .reg .u64 t; cvta.to.shared.u64 t, %1; cvt.u32.u64 %0, t; }" : "=r"(a) : "l"(p));
    return a;
}
// 128B-row tile offset, 16B chunk XOR swizzle (conflict-free ldmatrix + cp.async)
__device__ __forceinline__ uint32_t swz(int row, int ch) {
    return (uint32_t)(row * 128 + ((ch ^ (row & 7)) << 4));
}
#define CP_ASYNC16(sdst, gsrc) \
    asm volatile("cp.async.cg.shared.global [%0], [%1], 16;" :: "r"(sdst), "l"(gsrc))
#define CP_COMMIT() asm volatile("cp.async.commit_group;" ::: "memory")
#define CP_WAIT1()  asm volatile("cp.async.wait_group 1;" ::: "memory")
#define CP_WAIT0()  asm volatile("cp.async.wait_group 0;" ::: "memory")

__device__ __forceinline__ void ldmx4(uint32_t* r, uint32_t addr) {
    asm volatile("ldmatrix.sync.aligned.m8n8.x4.shared.b16 {%0,%1,%2,%3}, [%4];"
        : "=r"(r[0]), "=r"(r[1]), "=r"(r[2]), "=r"(r[3]) : "r"(addr));
}
__device__ __forceinline__ void mma_f16(float* c, const uint32_t* a, uint32_t b0, uint32_t b1) {
    asm volatile("mma.sync.aligned.m16n8k16.row.col.f32.f16.f16.f32 "
        "{%0,%1,%2,%3}, {%4,%5,%6,%7}, {%8,%9}, {%0,%1,%2,%3};"
        : "+f"(c[0]), "+f"(c[1]), "+f"(c[2]), "+f"(c[3])
        : "r"(a[0]), "r"(a[1]), "r"(a[2]), "r"(a[3]), "r"(b0), "r"(b1));
}

// ---------------------------------------------------------------------------
// Conversions to fp16 (rn)
// ---------------------------------------------------------------------------
__global__ void __launch_bounds__(512)
conv_x_kernel(const float* __restrict__ src)
{
    size_t i = ((size_t)blockIdx.x * 512 + threadIdx.x) * 16;
    float f[16];
    #pragma unroll
    for (int q = 0; q < 4; q++)
        *(float4*)&f[q * 4] = *(const float4*)(src + i + q * 4);
    __half h[16];
    #pragma unroll
    for (int j = 0; j < 16; j++) h[j] = __float2half_rn(f[j]);
    *(uint4*)&g_xh[i]     = *(uint4*)&h[0];
    *(uint4*)&g_xh[i + 8] = *(uint4*)&h[8];
}
__global__ void __launch_bounds__(256)
conv_w_kernel(const float* __restrict__ src)
{
    size_t i = ((size_t)blockIdx.x * 256 + threadIdx.x) * 8;
    float f[8];
    *(float4*)&f[0] = *(const float4*)(src + i);
    *(float4*)&f[4] = *(const float4*)(src + i + 4);
    __half h[8];
    #pragma unroll
    for (int j = 0; j < 8; j++) h[j] = __float2half_rn(f[j]);
    *(uint4*)&g_wh[i] = *(uint4*)h;
}

// ---------------------------------------------------------------------------
// fp16 single-term tensor-core GEMM, fused (a,v) epilogue + in-CTA segment
// scan (pass1). B tile rows interleave z / h_inter.
// ---------------------------------------------------------------------------
__global__ void __launch_bounds__(256, 2)
gemm_hmma_kernel(const float* __restrict__ b)
{
    extern __shared__ char dynsmem[];
    __shared__ float pA[64][4], pB[64][4];
    const uint32_t sbase = smem_u32(dynsmem);

    const int tid = threadIdx.x;
    const int wid = tid >> 5;
    const int l   = tid & 31;
    const int wm  = wid & 3;          // warp m: rows wm*32..+31
    const int wn  = wid >> 2;         // warp n: B rows wn*64..+63
    const int m0  = blockIdx.y * BM;
    const int o0p = blockIdx.x * BNP;

    // cp.async mapping: per tile, thread loads entries e = tid*4 + i (1024 total)
    const __half *sA[4], *sB[4];
    uint32_t dst[4];
    #pragma unroll
    for (int i = 0; i < 4; i++) {
        int e = tid * 4 + i;
        int row = e >> 3, ch = e & 7;
        sA[i] = g_xh + (size_t)(m0 + row) * KB + ch * 8;
        int wrow = (row & 1) ? (HB + o0p + (row >> 1)) : (o0p + (row >> 1));
        sB[i] = g_wh + (size_t)wrow * KB + ch * 8;
        dst[i] = swz(row, ch);
    }

    float acc[2][8][4];
    #pragma unroll
    for (int a0 = 0; a0 < 2; a0++)
        #pragma unroll
        for (int a1 = 0; a1 < 8; a1++)
            #pragma unroll
            for (int a2 = 0; a2 < 4; a2++) acc[a0][a1][a2] = 0.f;

    // prologue: fill PIPE-1 = 2 stages
    #pragma unroll
    for (int s = 0; s < PIPE - 1; s++) {
        uint32_t st = sbase + s * STAGE_BYTES;
        int ko = s * BKE;
        #pragma unroll
        for (int i = 0; i < 4; i++) {
            CP_ASYNC16(st + T_A + dst[i], sA[i] + ko);
            CP_ASYNC16(st + T_B + dst[i], sB[i] + ko);
        }
        CP_COMMIT();
    }

    const int lrow  = l & 15;
    const int lchnk = l >> 4;

    for (int kt = 0; kt < NKT; kt++) {
        CP_WAIT1();
        __syncthreads();

        int ktn = kt + PIPE - 1;
        if (ktn < NKT) {
            uint32_t stl = sbase + (ktn % PIPE) * STAGE_BYTES;
            int ko = ktn * BKE;
            #pragma unroll
            for (int i = 0; i < 4; i++) {
                CP_ASYNC16(stl + T_A + dst[i], sA[i] + ko);
                CP_ASYNC16(stl + T_B + dst[i], sB[i] + ko);
            }
        }
        CP_COMMIT();

        const uint32_t st = sbase + (kt % PIPE) * STAGE_BYTES;
        #pragma unroll
        for (int s = 0; s < 4; s++) {
            uint32_t a[2][4], bm[4][4];
            #pragma unroll
            for (int mt = 0; mt < 2; mt++) {
                int row = wm * 32 + mt * 16 + lrow;
                ldmx4(a[mt], st + T_A + swz(row, 2 * s + lchnk));
            }
            #pragma unroll
            for (int nt = 0; nt < 4; nt++) {
                int row = wn * 64 + nt * 16 + lrow;
                ldmx4(bm[nt], st + T_B + swz(row, 2 * s + lchnk));
            }
            #pragma unroll
            for (int mt = 0; mt < 2; mt++)
                #pragma unroll
                for (int nt = 0; nt < 4; nt++) {
                    mma_f16(acc[mt][nt * 2],     a[mt], bm[nt][0], bm[nt][2]);
                    mma_f16(acc[mt][nt * 2 + 1], a[mt], bm[nt][1], bm[nt][3]);
                }
        }
    }
    CP_WAIT0();
    __syncthreads();                         // stage smem now dead -> reuse as av tile

    __half2* av_s = (__half2*)dynsmem;       // [row][col] stride AV_STRIDE

    // ---- compute (a, v) into smem ----
    #pragma unroll
    for (int mt = 0; mt < 2; mt++) {
        #pragma unroll
        for (int nt8 = 0; nt8 < 8; nt8++) {
            int colloc = wn * 32 + nt8 * 4 + (l & 3);
            int o = o0p + colloc;
            float bz  = __ldg(b + o);
            float bh_ = __ldg(b + HB + o);
            #pragma unroll
            for (int half = 0; half < 2; half++) {
                int row = wm * 32 + mt * 16 + (l >> 2) + half * 8;
                float z   = acc[mt][nt8][half * 2]     + bz;
                float hin = acc[mt][nt8][half * 2 + 1] + bh_;
                float t   = __expf(-fabsf(z));
                float inv = 1.0f / (1.0f + t);
                float sig = (z >= 0.f) ? inv : t * inv;   // sigmoid(z)
                float av  = (z >= 0.f) ? t * inv : inv;   // sigmoid(-z)
                float gt;
                if (hin >= 0.f) gt = hin + 0.5f;
                else { float t2 = __expf(hin); gt = t2 / (1.f + t2); }
                av_s[row * AV_STRIDE + colloc] = __floats2half2_rn(av, sig * gt);
            }
        }
    }
    __syncthreads();

    // ---- coalesced g_av store: 2048 x 16B units, 8 per thread ----
    #pragma unroll
    for (int it = 0; it < 8; it++) {
        int e   = tid + it * 256;
        int row = e >> 4;
        int cg  = (e & 15) * 4;
        uint4 pk;
        pk.x = *(uint32_t*)&av_s[row * AV_STRIDE + cg + 0];
        pk.y = *(uint32_t*)&av_s[row * AV_STRIDE + cg + 1];
        pk.z = *(uint32_t*)&av_s[row * AV_STRIDE + cg + 2];
        pk.w = *(uint32_t*)&av_s[row * AV_STRIDE + cg + 3];
        *(uint4*)&g_av[(size_t)(m0 + row) * HB + o0p + cg] = pk;
    }

    // ---- in-CTA segment scan (replaces pass1): 4 threads/col x 32 rows ----
    {
        int col  = tid >> 2;
        int part = tid & 3;
        float A = 1.f, B = 0.f;
        int r0 = part * 32;
        #pragma unroll 4
        for (int r = r0; r < r0 + 32; r++) {
            float2 av = __half22float2(av_s[r * AV_STRIDE + col]);
            B = fmaf(av.x, B, av.y);
            A *= av.x;
        }
        pA[col][part] = A;
        pB[col][part] = B;
    }
    __syncthreads();
    if (tid < 64) {
        float Ac = pA[tid][0], Bc = pB[tid][0];
        #pragma unroll
        for (int p = 1; p < 4; p++) {
            Bc = fmaf(pA[tid][p], Bc, pB[tid][p]);
            Ac *= pA[tid][p];
        }
        int segi = m0 >> 7;                    // = n*SEG + seg
        g_Aseg[segi * HB + o0p + tid] = Ac;
        g_Bseg[segi * HB + o0p + tid] = Bc;
    }
}

// ---------------------------------------------------------------------------
// pass2: sequential scan over segment summaries per (n, h)
// ---------------------------------------------------------------------------
__global__ void __launch_bounds__(256)
scan_pass2(const float* __restrict__ hx)
{
    int h = blockIdx.x * 256 + threadIdx.x;
    int n = blockIdx.y;
    float hcur = hx[n * HB + h];
    for (int s = 0; s < SEG; s++) {
        int idx = (n * SEG + s) * HB + h;
        g_Cin[idx] = hcur;
        hcur = fmaf(g_Aseg[idx], hcur, g_Bseg[idx]);
    }
}

// ---------------------------------------------------------------------------
// pass3: re-scan each segment from carry-in, 4 h per thread, 16B ld/st
// ---------------------------------------------------------------------------
__global__ void __launch_bounds__(256)
scan_pass3(float* __restrict__ out)
{
    int h0  = threadIdx.x * 4;
    int seg = blockIdx.y;
    int n   = blockIdx.z;
    size_t base = ((size_t)(n * LB + seg * SEGLEN)) * HB + h0;

    float4 hc = *(float4*)&g_Cin[(n * SEG + seg) * HB + h0];
    float* hcp = (float*)&hc;
    #pragma unroll 4
    for (int i = 0; i < SEGLEN; i++) {
        uint4 raw = *(uint4*)&g_av[base + (size_t)i * HB];
        const uint32_t* rp = (const uint32_t*)&raw;
        float4 o;
        float* op = (float*)&o;
        #pragma unroll
        for (int j = 0; j < 4; j++) {
            float2 av = __half22float2(*(const __half2*)&rp[j]);
            hcp[j] = fmaf(av.x, hcp[j], av.y);
            op[j] = hcp[j];
        }
        *(float4*)&out[base + (size_t)i * HB] = o;
    }
}

// ---------------------------------------------------------------------------
extern "C" void kernel_launch(void* const* d_in, const int* in_sizes, int n_in,
                              void* d_out, int out_size)
{
    const float *x = nullptr, *W = nullptr, *b = nullptr, *hx = nullptr;
    for (int i = 0; i < n_in; i++) {
        switch (in_sizes[i]) {
            case 33554432: x  = (const float*)d_in[i]; break;
            case 2097152:  W  = (const float*)d_in[i]; break;
            case 2048:     b  = (const float*)d_in[i]; break;
            case 8192:     hx = (const float*)d_in[i]; break;
        }
    }
    float* out = (float*)d_out;

    cudaFuncSetAttribute(gemm_hmma_kernel, cudaFuncAttributeMaxDynamicSharedMemorySize, SMEM_DYN);

    conv_w_kernel<<<(size_t)2 * HB * KB / 8 / 256, 256>>>(W);
    conv_x_kernel<<<(size_t)MTOT * KB / 16 / 512, 512>>>(x);

    dim3 gemm_grid(HB / BNP, MTOT / BM);   // (16, 256)
    gemm_hmma_kernel<<<gemm_grid, 256, SMEM_DYN>>>(b);

    scan_pass2<<<dim3(HB / 256, NB), 256>>>(hx);
    scan_pass3<<<dim3(1, SEG, NB), 256>>>(out);
}

// round 15
// speedup vs baseline: 1.4922x; 1.4922x over previous
#include <cuda_runtime.h>
#include <cuda_fp16.h>
#include <cstdint>
#include <math.h>

// ---------------- problem dims ----------------
#define NB   8
#define LB   4096
#define HB   1024
#define KB   1024
#define MTOT (NB * LB)          // 32768
#define SEG    32
#define SEGLEN (LB / SEG)       // 128

// ---------------- GEMM tiling -----------------
#define BM 128                  // M rows / CTA
#define BNP 64                  // o-pairs / CTA (B tile = 128 interleaved rows)
#define BKE 64                  // K fp16 elems per stage (128B rows)
#define NKT (KB / BKE)          // 16
#define PIPE 3

// per-stage smem tiles (bytes): 128 rows x 128B each
#define T_A  0
#define T_B  16384
#define STAGE_BYTES 32768
#define SMEM_DYN (PIPE * STAGE_BYTES)   // 96 KB -> 2 CTAs/SM

// ---------------- device scratch ----------------
__device__ __half2 g_av[(size_t)MTOT * HB];    // packed (a, v) = 128 MB
__device__ float  g_Aseg[NB * SEG * HB];
__device__ float  g_Bseg[NB * SEG * HB];
__device__ float  g_Cin [NB * SEG * HB];
__device__ __half g_xh[(size_t)MTOT * KB];     // 64 MB
__device__ __half g_wh[(size_t)2 * HB * KB];   // 4 MB

// ---------------- helpers ----------------
__device__ __forceinline__ uint32_t smem_u32(const void* p) {
    uint32_t a;
    asm("{ .reg .u64 t; cvta.to.shared.u64 t, %1; cvt.u32.u64 %0, t; }" : "=r"(a) : "l"(p));
    return a;
}
// 128B-row tile offset, 16B chunk XOR swizzle (conflict-free ldmatrix + cp.async)
__device__ __forceinline__ uint32_t swz(int row, int ch) {
    return (uint32_t)(row * 128 + ((ch ^ (row & 7)) << 4));
}
#define CP_ASYNC16(sdst, gsrc) \
    asm volatile("cp.async.cg.shared.global [%0], [%1], 16;" :: "r"(sdst), "l"(gsrc))
#define CP_COMMIT() asm volatile("cp.async.commit_group;" ::: "memory")
#define CP_WAIT1()  asm volatile("cp.async.wait_group 1;" ::: "memory")
#define CP_WAIT0()  asm volatile("cp.async.wait_group 0;" ::: "memory")

__device__ __forceinline__ void ldmx4(uint32_t* r, uint32_t addr) {
    asm volatile("ldmatrix.sync.aligned.m8n8.x4.shared.b16 {%0,%1,%2,%3}, [%4];"
        : "=r"(r[0]), "=r"(r[1]), "=r"(r[2]), "=r"(r[3]) : "r"(addr));
}
__device__ __forceinline__ void mma_f16(float* c, const uint32_t* a, uint32_t b0, uint32_t b1) {
    asm volatile("mma.sync.aligned.m16n8k16.row.col.f32.f16.f16.f32 "
        "{%0,%1,%2,%3}, {%4,%5,%6,%7}, {%8,%9}, {%0,%1,%2,%3};"
        : "+f"(c[0]), "+f"(c[1]), "+f"(c[2]), "+f"(c[3])
        : "r"(a[0]), "r"(a[1]), "r"(a[2]), "r"(a[3]), "r"(b0), "r"(b1));
}

// ---------------------------------------------------------------------------
// Conversions to fp16 (rn)
// ---------------------------------------------------------------------------
__global__ void __launch_bounds__(512)
conv_x_kernel(const float* __restrict__ src)
{
    size_t i = ((size_t)blockIdx.x * 512 + threadIdx.x) * 16;
    float f[16];
    #pragma unroll
    for (int q = 0; q < 4; q++)
        *(float4*)&f[q * 4] = *(const float4*)(src + i + q * 4);
    __half h[16];
    #pragma unroll
    for (int j = 0; j < 16; j++) h[j] = __float2half_rn(f[j]);
    *(uint4*)&g_xh[i]     = *(uint4*)&h[0];
    *(uint4*)&g_xh[i + 8] = *(uint4*)&h[8];
}
__global__ void __launch_bounds__(256)
conv_w_kernel(const float* __restrict__ src)
{
    size_t i = ((size_t)blockIdx.x * 256 + threadIdx.x) * 8;
    float f[8];
    *(float4*)&f[0] = *(const float4*)(src + i);
    *(float4*)&f[4] = *(const float4*)(src + i + 4);
    __half h[8];
    #pragma unroll
    for (int j = 0; j < 8; j++) h[j] = __float2half_rn(f[j]);
    *(uint4*)&g_wh[i] = *(uint4*)h;
}

// ---------------------------------------------------------------------------
// fp16 single-term tensor-core GEMM with fused (a, v) epilogue (fp16 packed).
// IDENTICAL to the 647us R11 kernel.
// ---------------------------------------------------------------------------
__global__ void __launch_bounds__(256, 2)
gemm_hmma_kernel(const float* __restrict__ b)
{
    extern __shared__ char dynsmem[];
    const uint32_t sbase = smem_u32(dynsmem);

    const int tid = threadIdx.x;
    const int wid = tid >> 5;
    const int l   = tid & 31;
    const int wm  = wid & 3;          // warp m: rows wm*32..+31
    const int wn  = wid >> 2;         // warp n: B rows wn*64..+63
    const int m0  = blockIdx.y * BM;
    const int o0p = blockIdx.x * BNP;

    // cp.async mapping: per tile, thread loads entries e = tid*4 + i (1024 total)
    const __half *sA[4], *sB[4];
    uint32_t dst[4];
    #pragma unroll
    for (int i = 0; i < 4; i++) {
        int e = tid * 4 + i;
        int row = e >> 3, ch = e & 7;
        sA[i] = g_xh + (size_t)(m0 + row) * KB + ch * 8;
        int wrow = (row & 1) ? (HB + o0p + (row >> 1)) : (o0p + (row >> 1));
        sB[i] = g_wh + (size_t)wrow * KB + ch * 8;
        dst[i] = swz(row, ch);
    }

    float acc[2][8][4];
    #pragma unroll
    for (int a0 = 0; a0 < 2; a0++)
        #pragma unroll
        for (int a1 = 0; a1 < 8; a1++)
            #pragma unroll
            for (int a2 = 0; a2 < 4; a2++) acc[a0][a1][a2] = 0.f;

    // prologue: fill PIPE-1 = 2 stages
    #pragma unroll
    for (int s = 0; s < PIPE - 1; s++) {
        uint32_t st = sbase + s * STAGE_BYTES;
        int ko = s * BKE;
        #pragma unroll
        for (int i = 0; i < 4; i++) {
            CP_ASYNC16(st + T_A + dst[i], sA[i] + ko);
            CP_ASYNC16(st + T_B + dst[i], sB[i] + ko);
        }
        CP_COMMIT();
    }

    const int lrow  = l & 15;
    const int lchnk = l >> 4;    // 16B half of the 32B k16 slice

    for (int kt = 0; kt < NKT; kt++) {
        CP_WAIT1();              // oldest stage (kt) complete
        __syncthreads();

        // front-load next-stage loads (target buffer consumed last iteration)
        int ktn = kt + PIPE - 1;
        if (ktn < NKT) {
            uint32_t stl = sbase + (ktn % PIPE) * STAGE_BYTES;
            int ko = ktn * BKE;
            #pragma unroll
            for (int i = 0; i < 4; i++) {
                CP_ASYNC16(stl + T_A + dst[i], sA[i] + ko);
                CP_ASYNC16(stl + T_B + dst[i], sB[i] + ko);
            }
        }
        CP_COMMIT();   // unconditional: keeps wait_group invariant

        const uint32_t st = sbase + (kt % PIPE) * STAGE_BYTES;
        #pragma unroll
        for (int s = 0; s < 4; s++) {           // four k16 steps per stage
            uint32_t a[2][4], bm[4][4];
            #pragma unroll
            for (int mt = 0; mt < 2; mt++) {
                int row = wm * 32 + mt * 16 + lrow;
                ldmx4(a[mt], st + T_A + swz(row, 2 * s + lchnk));
            }
            #pragma unroll
            for (int nt = 0; nt < 4; nt++) {
                int row = wn * 64 + nt * 16 + lrow;
                ldmx4(bm[nt], st + T_B + swz(row, 2 * s + lchnk));
            }
            #pragma unroll
            for (int mt = 0; mt < 2; mt++)
                #pragma unroll
                for (int nt = 0; nt < 4; nt++) {
                    mma_f16(acc[mt][nt * 2],     a[mt], bm[nt][0], bm[nt][2]);
                    mma_f16(acc[mt][nt * 2 + 1], a[mt], bm[nt][1], bm[nt][3]);
                }
        }
    }
    CP_WAIT0();

    // ------------- epilogue: even B-row = z, odd = h_inter of same o
    #pragma unroll
    for (int mt = 0; mt < 2; mt++) {
        #pragma unroll
        for (int nt8 = 0; nt8 < 8; nt8++) {
            int o = o0p + wn * 32 + nt8 * 4 + (l & 3);
            float bz  = __ldg(b + o);
            float bh_ = __ldg(b + HB + o);
            #pragma unroll
            for (int half = 0; half < 2; half++) {
                int m = m0 + wm * 32 + mt * 16 + (l >> 2) + half * 8;
                float z   = acc[mt][nt8][half * 2]     + bz;
                float hin = acc[mt][nt8][half * 2 + 1] + bh_;
                float t   = __expf(-fabsf(z));
                float inv = 1.0f / (1.0f + t);
                float sig = (z >= 0.f) ? inv : t * inv;   // sigmoid(z)
                float av  = (z >= 0.f) ? t * inv : inv;   // sigmoid(-z)
                float gt;
                if (hin >= 0.f) gt = hin + 0.5f;
                else { float t2 = __expf(hin); gt = t2 / (1.f + t2); }
                size_t idx = (size_t)m * HB + o;
                g_av[idx] = __floats2half2_rn(av, sig * gt);
            }
        }
    }
}

// ---------------------------------------------------------------------------
// pass1: per-segment affine composition, 4 h per thread, 16B loads
// ---------------------------------------------------------------------------
__global__ void __launch_bounds__(256)
scan_pass1(void)
{
    int h0  = threadIdx.x * 4;
    int seg = blockIdx.y;
    int n   = blockIdx.z;
    size_t base = ((size_t)(n * LB + seg * SEGLEN)) * HB + h0;

    float A[4] = {1.f, 1.f, 1.f, 1.f};
    float B[4] = {0.f, 0.f, 0.f, 0.f};
    #pragma unroll 4
    for (int i = 0; i < SEGLEN; i++) {
        uint4 raw = *(const uint4*)&g_av[base + (size_t)i * HB];
        const uint32_t* rp = (const uint32_t*)&raw;
        #pragma unroll
        for (int j = 0; j < 4; j++) {
            float2 av = __half22float2(*(const __half2*)&rp[j]);
            B[j] = fmaf(av.x, B[j], av.y);
            A[j] *= av.x;
        }
    }
    int idx = (n * SEG + seg) * HB + h0;
    *(float4*)&g_Aseg[idx] = *(float4*)A;
    *(float4*)&g_Bseg[idx] = *(float4*)B;
}

// ---------------------------------------------------------------------------
// pass2: sequential scan over segment summaries per (n, h)
// ---------------------------------------------------------------------------
__global__ void __launch_bounds__(256)
scan_pass2(const float* __restrict__ hx)
{
    int h = blockIdx.x * 256 + threadIdx.x;
    int n = blockIdx.y;
    float hcur = hx[n * HB + h];
    for (int s = 0; s < SEG; s++) {
        int idx = (n * SEG + s) * HB + h;
        g_Cin[idx] = hcur;
        hcur = fmaf(g_Aseg[idx], hcur, g_Bseg[idx]);
    }
}

// ---------------------------------------------------------------------------
// pass3: re-scan each segment from carry-in (R11 layout, 1 h per thread)
// ---------------------------------------------------------------------------
__global__ void __launch_bounds__(256)
scan_pass3(float* __restrict__ out)
{
    int h   = blockIdx.x * 256 + threadIdx.x;
    int seg = blockIdx.y;
    int n   = blockIdx.z;
    size_t base = ((size_t)(n * LB + seg * SEGLEN)) * HB + h;
    float hcur = g_Cin[(n * SEG + seg) * HB + h];
    #pragma unroll 4
    for (int i = 0; i < SEGLEN; i++) {
        float2 av = __half22float2(g_av[base + (size_t)i * HB]);
        hcur = fmaf(av.x, hcur, av.y);
        out[base + (size_t)i * HB] = hcur;
    }
}

// ---------------------------------------------------------------------------
extern "C" void kernel_launch(void* const* d_in, const int* in_sizes, int n_in,
                              void* d_out, int out_size)
{
    const float *x = nullptr, *W = nullptr, *b = nullptr, *hx = nullptr;
    for (int i = 0; i < n_in; i++) {
        switch (in_sizes[i]) {
            case 33554432: x  = (const float*)d_in[i]; break;
            case 2097152:  W  = (const float*)d_in[i]; break;
            case 2048:     b  = (const float*)d_in[i]; break;
            case 8192:     hx = (const float*)d_in[i]; break;
        }
    }
    float* out = (float*)d_out;

    cudaFuncSetAttribute(gemm_hmma_kernel, cudaFuncAttributeMaxDynamicSharedMemorySize, SMEM_DYN);

    conv_w_kernel<<<(size_t)2 * HB * KB / 8 / 256, 256>>>(W);
    conv_x_kernel<<<(size_t)MTOT * KB / 16 / 512, 512>>>(x);

    dim3 gemm_grid(HB / BNP, MTOT / BM);   // (16, 256)
    gemm_hmma_kernel<<<gemm_grid, 256, SMEM_DYN>>>(b);

    scan_pass1<<<dim3(1, SEG, NB), 256>>>();
    scan_pass2<<<dim3(HB / 256, NB), 256>>>(hx);
    scan_pass3<<<dim3(HB / 256, SEG, NB), 256>>>(out);
}